// round 9
// baseline (speedup 1.0000x reference)
#include <cuda_runtime.h>
#include <math.h>
#include <stdint.h>

#define B_  2048
#define N_  64
#define H_  512
#define L_  256
#define M_  (B_*N_)    // 131072 edges

// ---------------- scratch ----------------
__device__ float g_mu [ (size_t)M_ * L_ ];
__device__ float g_lv [ (size_t)M_ * L_ ];
__device__ float g_mean[M_];
__device__ float g_rstd[M_];
__device__ float g_bias[M_];
__device__ float g_qk  [B_ * L_];
__device__ float g_qkb [B_];
__device__ float g_ctx [B_ * L_];
__device__ float g_sw  [B_];
__device__ float g_klsum;
__device__ float g_nmsum;
// pre-converted tf32 weights, TRANSPOSED to [n][k] (k pitch = H_)
__device__ uint32_t g_muw_t [L_ * H_];
__device__ uint32_t g_lvw_t [L_ * H_];
__device__ uint32_t g_bm1w_t[H_ * H_];

// ---------------- helpers ----------------
__device__ __forceinline__ uint32_t f2tf(float x){
    uint32_t u; asm("cvt.rna.tf32.f32 %0, %1;" : "=r"(u) : "f"(x)); return u;
}
__device__ __forceinline__ void mma_tf32(float4& d, const uint32_t a[4], const uint32_t b[2]){
    asm volatile("mma.sync.aligned.m16n8k8.row.col.f32.tf32.tf32.f32 "
        "{%0,%1,%2,%3}, {%4,%5,%6,%7}, {%8,%9}, {%0,%1,%2,%3};\n"
        : "+f"(d.x), "+f"(d.y), "+f"(d.z), "+f"(d.w)
        : "r"(a[0]), "r"(a[1]), "r"(a[2]), "r"(a[3]), "r"(b[0]), "r"(b[1]));
}
__device__ __forceinline__ void ldsm_x4(uint32_t a[4], uint32_t addr){
    asm volatile("ldmatrix.sync.aligned.m8n8.x4.shared.b16 {%0,%1,%2,%3}, [%4];"
        : "=r"(a[0]), "=r"(a[1]), "=r"(a[2]), "=r"(a[3]) : "r"(addr));
}
__device__ __forceinline__ void ldsm_x2(uint32_t b[2], uint32_t addr){
    asm volatile("ldmatrix.sync.aligned.m8n8.x2.shared.b16 {%0,%1}, [%2];"
        : "=r"(b[0]), "=r"(b[1]) : "r"(addr));
}
__device__ __forceinline__ float warpSum(float v){
    #pragma unroll
    for (int o = 16; o; o >>= 1) v += __shfl_xor_sync(0xffffffffu, v, o);
    return v;
}
__device__ __forceinline__ void cp16(uint32_t dst, const void* src){
    asm volatile("cp.async.cg.shared.global [%0], [%1], 16;" :: "r"(dst), "l"(src));
}
#define CP_COMMIT() asm volatile("cp.async.commit_group;")
#define CP_WAIT0()  asm volatile("cp.async.wait_group 0;")

// ---------------- KW: convert weights to tf32, transposed [n][k] ----------------
__global__ void kw_conv(const float* __restrict__ mu_w, const float* __restrict__ lv_w,
                        const float* __restrict__ bm1_w){
    int i = blockIdx.x * 256 + threadIdx.x;   // covers H_*H_
    int n = i >> 9, k = i & 511;
    g_bm1w_t[i] = f2tf(bm1_w[(size_t)k * H_ + n]);
    if (n < L_){
        g_muw_t[i] = f2tf(mu_w[(size_t)k * L_ + n]);
        g_lvw_t[i] = f2tf(lv_w[(size_t)k * L_ + n]);
    }
}

// ---------------- K0: per-row LN stats (warp per row) + zero accumulators --------
__global__ void k0_stats(const float* __restrict__ neigh){
    int row = blockIdx.x * 8 + (threadIdx.x >> 5);
    int lane = threadIdx.x & 31;
    const float4* x = (const float4*)(neigh + (size_t)row * H_);
    float s = 0.f, ss = 0.f;
    #pragma unroll
    for (int i = 0; i < 4; i++){
        float4 v = x[lane + 32 * i];
        s  += v.x + v.y + v.z + v.w;
        ss += v.x*v.x + v.y*v.y + v.z*v.z + v.w*v.w;
    }
    s = warpSum(s); ss = warpSum(ss);
    if (lane == 0){
        float mean = s * (1.f / 512.f);
        float var  = ss * (1.f / 512.f) - mean * mean;
        g_mean[row] = mean;
        g_rstd[row] = rsqrtf(var + 1e-5f);
        g_bias[row] = 0.f;
        if (row == 0){ g_klsum = 0.f; g_nmsum = 0.f; }
    }
}

// ---------------- K1: query = self@q_w + q_b ; qk = query@k_w^T ; qkb = query.k_b --
__global__ void k1_query(const float* __restrict__ self,
                         const float* __restrict__ q_w, const float* __restrict__ q_b,
                         const float* __restrict__ k_w, const float* __restrict__ k_b){
    __shared__ float s_self[8][H_];
    __shared__ float s_q[8][L_];
    int b0 = blockIdx.x * 8;
    int tid = threadIdx.x;
    for (int idx = tid; idx < 8 * H_; idx += 256){
        int r = idx >> 9, h = idx & 511;
        s_self[r][h] = self[(size_t)(b0 + r) * H_ + h];
    }
    __syncthreads();
    {
        float acc[8] = {};
        for (int h = 0; h < H_; h++){
            float w = q_w[(size_t)h * L_ + tid];
            #pragma unroll
            for (int r = 0; r < 8; r++) acc[r] += s_self[r][h] * w;
        }
        float qb = q_b[tid];
        #pragma unroll
        for (int r = 0; r < 8; r++) s_q[r][tid] = acc[r] + qb;
    }
    __syncthreads();
    {
        float acc[8] = {};
        for (int l = 0; l < L_; l++){
            float w = k_w[(size_t)tid * L_ + l];
            #pragma unroll
            for (int r = 0; r < 8; r++) acc[r] += s_q[r][l] * w;
        }
        #pragma unroll
        for (int r = 0; r < 8; r++) g_qk[(size_t)(b0 + r) * L_ + tid] = acc[r];
    }
    int w = tid >> 5, lane = tid & 31;
    float p = 0.f;
    for (int l = lane; l < L_; l += 32) p += s_q[w][l] * k_b[l];
    p = warpSum(p);
    if (lane == 0) g_qkb[b0 + w] = p;
}

// ---------------- K2: fused tf32 GEMM, 128 threads, warp tile 64x64, ldmatrix ----
// grid = (8, M_/128). blockIdx.x = n-slice:
//   yy 0,1: mu cols; yy 2,3: lv cols; yy 4..7: bias-MLP cols
#define BMg 128
#define BNg 128
#define BKg 16
#define APITCH 20
#define BPITCH 20

__global__ __launch_bounds__(128, 2)
void gemm_fused(const float* __restrict__ neigh, const float* __restrict__ self,
                const float* __restrict__ pre_w, const float* __restrict__ pre_b,
                const float* __restrict__ mu_b, const float* __restrict__ lv_b,
                const float* __restrict__ bm1_b, const float* __restrict__ bm2w){
    __shared__ __align__(16) uint32_t As[2][BMg * APITCH];   // [m][k] pitch 20
    __shared__ __align__(16) uint32_t Bs[2][BNg * BPITCH];   // [n][k] pitch 20
    __shared__ float s_mean[BMg], s_rstd[BMg];
    __shared__ float s_prew[H_], s_preb[H_];
    __shared__ float brow[BMg];

    int yy = blockIdx.x;
    int m0 = blockIdx.y * BMg;
    int tid = threadIdx.x;            // 0..127
    int lane = tid & 31, w = tid >> 5;   // 4 warps
    bool isBias = (yy >= 4);

    const uint32_t* Bw; const float* biasv; float* C = nullptr; int n0;
    if (yy < 2){ Bw = g_muw_t; biasv = mu_b; C = g_mu; n0 = yy * 128; }
    else if (yy < 4){ Bw = g_lvw_t; biasv = lv_b; C = g_lv; n0 = (yy - 2) * 128; }
    else { Bw = g_bm1w_t; biasv = bm1_b; n0 = (yy - 4) * 128; }

    if (!isBias){
        s_mean[tid] = g_mean[m0 + tid];
        s_rstd[tid] = g_rstd[m0 + tid];
        for (int i = tid; i < H_; i += 128){
            s_prew[i] = pre_w[i]; s_preb[i] = pre_b[i];
        }
        __syncthreads();
    }

    int am = tid >> 2;            // 0..31
    int ak = (tid & 3) * 4;       // 0,4,8,12
    int wm = (w & 1) * 64;
    int wn = (w >> 1) * 64;

    // ldmatrix per-lane address components
    int rowA = (lane & 7) + ((lane >> 3) & 1) * 8;
    int kqA  = (lane >> 4) * 4;
    int rowB = lane & 7;
    int kqB  = ((lane >> 3) & 1) * 4;

    uint32_t as0 = (uint32_t)__cvta_generic_to_shared(&As[0][0]);
    uint32_t as1 = (uint32_t)__cvta_generic_to_shared(&As[1][0]);
    uint32_t bs0 = (uint32_t)__cvta_generic_to_shared(&Bs[0][0]);
    uint32_t bs1 = (uint32_t)__cvta_generic_to_shared(&Bs[1][0]);

    float4 acc[4][8];
    #pragma unroll
    for (int i = 0; i < 4; i++)
        #pragma unroll
        for (int j = 0; j < 8; j++) acc[i][j] = make_float4(0.f, 0.f, 0.f, 0.f);

    const int KT = H_ / BKg;     // 32
    float4 vA[4], vS[4];

    auto LDG_A = [&](int kt){
        int k0 = kt * BKg;
        #pragma unroll
        for (int h = 0; h < 4; h++){
            int m = am + 32 * h;
            vA[h] = *(const float4*)(neigh + (size_t)(m0 + m) * H_ + k0 + ak);
            if (isBias)
                vS[h] = *(const float4*)(self + (size_t)((m0 + m) >> 6) * H_ + k0 + ak);
        }
    };
    auto CPA_B = [&](int kt, int buf){
        int k0 = kt * BKg;
        uint32_t base = buf ? bs1 : bs0;
        const uint32_t* src = Bw + (size_t)(n0 + tid) * H_ + k0;
        uint32_t dst = base + (tid * BPITCH) * 4;
        #pragma unroll
        for (int c = 0; c < 4; c++) cp16(dst + c * 16, src + c * 4);
    };
    auto STS_A = [&](int buf, int kt){
        int k0 = kt * BKg;
        #pragma unroll
        for (int h = 0; h < 4; h++){
            int m = am + 32 * h;
            float x0, x1, x2, x3;
            if (!isBias){
                float mn = s_mean[m], rs = s_rstd[m];
                x0 = (vA[h].x - mn) * rs * s_prew[k0+ak+0] + s_preb[k0+ak+0];
                x1 = (vA[h].y - mn) * rs * s_prew[k0+ak+1] + s_preb[k0+ak+1];
                x2 = (vA[h].z - mn) * rs * s_prew[k0+ak+2] + s_preb[k0+ak+2];
                x3 = (vA[h].w - mn) * rs * s_prew[k0+ak+3] + s_preb[k0+ak+3];
            } else {
                x0 = fabsf(vS[h].x - vA[h].x); x1 = fabsf(vS[h].y - vA[h].y);
                x2 = fabsf(vS[h].z - vA[h].z); x3 = fabsf(vS[h].w - vA[h].w);
            }
            *(uint4*)&As[buf][m * APITCH + ak] =
                make_uint4(f2tf(x0), f2tf(x1), f2tf(x2), f2tf(x3));
        }
    };

    CPA_B(0, 0); CP_COMMIT();
    LDG_A(0); STS_A(0, 0);
    CP_WAIT0();
    __syncthreads();

    for (int kt = 0; kt < KT; kt++){
        int cur = kt & 1;
        uint32_t abase = cur ? as1 : as0;
        uint32_t bbase = cur ? bs1 : bs0;
        if (kt + 1 < KT){
            CPA_B(kt + 1, cur ^ 1); CP_COMMIT();
            LDG_A(kt + 1);
        }
        #pragma unroll
        for (int ks = 0; ks < 2; ks++){
            int kb = ks * 8;
            uint32_t af[4][4];
            #pragma unroll
            for (int mi = 0; mi < 4; mi++)
                ldsm_x4(af[mi], abase + ((wm + mi * 16 + rowA) * APITCH + kb + kqA) * 4);
            #pragma unroll
            for (int ni = 0; ni < 8; ni++){
                uint32_t bf[2];
                ldsm_x2(bf, bbase + ((wn + ni * 8 + rowB) * BPITCH + kb + kqB) * 4);
                #pragma unroll
                for (int mi = 0; mi < 4; mi++) mma_tf32(acc[mi][ni], af[mi], bf);
            }
        }
        if (kt + 1 < KT){
            STS_A(cur ^ 1, kt + 1);
            CP_WAIT0();
            __syncthreads();
        }
    }

    if (!isBias){
        #pragma unroll
        for (int mi = 0; mi < 4; mi++){
            int r0 = m0 + wm + mi * 16 + (lane >> 2);
            #pragma unroll
            for (int ni = 0; ni < 8; ni++){
                int c = n0 + wn + ni * 8 + 2 * (lane & 3);
                float b0 = biasv[c], b1 = biasv[c + 1];
                float4 a = acc[mi][ni];
                *(float2*)(C + (size_t)r0 * L_ + c)       = make_float2(a.x + b0, a.y + b1);
                *(float2*)(C + (size_t)(r0 + 8) * L_ + c) = make_float2(a.z + b0, a.w + b1);
            }
        }
    } else {
        brow[tid] = 0.f;
        __syncthreads();
        #pragma unroll
        for (int mi = 0; mi < 4; mi++){
            float s0 = 0.f, s1 = 0.f;
            #pragma unroll
            for (int ni = 0; ni < 8; ni++){
                int c = n0 + wn + ni * 8 + 2 * (lane & 3);
                float w0 = bm2w[c], w1 = bm2w[c + 1];
                float b0 = biasv[c], b1 = biasv[c + 1];
                float4 a = acc[mi][ni];
                s0 += fmaxf(a.x + b0, 0.f) * w0 + fmaxf(a.y + b1, 0.f) * w1;
                s1 += fmaxf(a.z + b0, 0.f) * w0 + fmaxf(a.w + b1, 0.f) * w1;
            }
            s0 += __shfl_xor_sync(0xffffffffu, s0, 1);
            s0 += __shfl_xor_sync(0xffffffffu, s0, 2);
            s1 += __shfl_xor_sync(0xffffffffu, s1, 1);
            s1 += __shfl_xor_sync(0xffffffffu, s1, 2);
            if ((lane & 3) == 0){
                atomicAdd(&brow[wm + mi * 16 + (lane >> 2)], s0);
                atomicAdd(&brow[wm + mi * 16 + (lane >> 2) + 8], s1);
            }
        }
        __syncthreads();
        atomicAdd(&g_bias[m0 + tid], brow[tid]);
    }
}

// ---------------- K34: fused z/LN/kl/dot + softmax + context (block per batch) ----
__global__ void k34_fused(const float* __restrict__ eps,
                          const float* __restrict__ post_w, const float* __restrict__ post_b,
                          const float* __restrict__ trust, const float* __restrict__ comm,
                          const float* __restrict__ bm2_b){
    extern __shared__ float zsh[];   // [64][L_] = 64 KB
    __shared__ float s_dot[N_], s_kl[N_], s_w[N_];
    int b = blockIdx.x, tid = threadIdx.x;
    int wi = tid >> 5, lane = tid & 31;

    float4 pw0 = *(const float4*)(post_w + lane * 4);
    float4 pw1 = *(const float4*)(post_w + 128 + lane * 4);
    float4 pb0 = *(const float4*)(post_b + lane * 4);
    float4 pb1 = *(const float4*)(post_b + 128 + lane * 4);
    float4 qv0 = *(const float4*)(g_qk + (size_t)b * L_ + lane * 4);
    float4 qv1 = *(const float4*)(g_qk + (size_t)b * L_ + 128 + lane * 4);

    #pragma unroll
    for (int j = 0; j < 8; j++){
        int n = wi * 8 + j;
        size_t base = ((size_t)(b * N_ + n)) * L_;
        float4 m0 = *(const float4*)(g_mu + base + lane * 4);
        float4 m1 = *(const float4*)(g_mu + base + 128 + lane * 4);
        float4 l0 = *(const float4*)(g_lv + base + lane * 4);
        float4 l1 = *(const float4*)(g_lv + base + 128 + lane * 4);
        float4 e0 = *(const float4*)(eps + base + lane * 4);
        float4 e1 = *(const float4*)(eps + base + 128 + lane * 4);
        float zp[8];
        zp[0] = m0.x + e0.x * expf(0.5f * l0.x);
        zp[1] = m0.y + e0.y * expf(0.5f * l0.y);
        zp[2] = m0.z + e0.z * expf(0.5f * l0.z);
        zp[3] = m0.w + e0.w * expf(0.5f * l0.w);
        zp[4] = m1.x + e1.x * expf(0.5f * l1.x);
        zp[5] = m1.y + e1.y * expf(0.5f * l1.y);
        zp[6] = m1.z + e1.z * expf(0.5f * l1.z);
        zp[7] = m1.w + e1.w * expf(0.5f * l1.w);
        float s = 0.f;
        #pragma unroll
        for (int i = 0; i < 8; i++) s += zp[i];
        float mean = warpSum(s) * (1.f / 256.f);
        float v = 0.f;
        #pragma unroll
        for (int i = 0; i < 8; i++){ float d = zp[i] - mean; v += d * d; }
        float rstd = rsqrtf(warpSum(v) * (1.f / 256.f) + 1e-5f);
        float4 z0, z1;
        z0.x = (zp[0] - mean) * rstd * pw0.x + pb0.x;
        z0.y = (zp[1] - mean) * rstd * pw0.y + pb0.y;
        z0.z = (zp[2] - mean) * rstd * pw0.z + pb0.z;
        z0.w = (zp[3] - mean) * rstd * pw0.w + pb0.w;
        z1.x = (zp[4] - mean) * rstd * pw1.x + pb1.x;
        z1.y = (zp[5] - mean) * rstd * pw1.y + pb1.y;
        z1.z = (zp[6] - mean) * rstd * pw1.z + pb1.z;
        z1.w = (zp[7] - mean) * rstd * pw1.w + pb1.w;
        *(float4*)(zsh + n * L_ + lane * 4)       = z0;
        *(float4*)(zsh + n * L_ + 128 + lane * 4) = z1;
        float dp = z0.x*qv0.x + z0.y*qv0.y + z0.z*qv0.z + z0.w*qv0.w
                 + z1.x*qv1.x + z1.y*qv1.y + z1.z*qv1.z + z1.w*qv1.w;
        dp = warpSum(dp);
        float kl = (1.f + l0.x - m0.x*m0.x - expf(l0.x))
                 + (1.f + l0.y - m0.y*m0.y - expf(l0.y))
                 + (1.f + l0.z - m0.z*m0.z - expf(l0.z))
                 + (1.f + l0.w - m0.w*m0.w - expf(l0.w))
                 + (1.f + l1.x - m1.x*m1.x - expf(l1.x))
                 + (1.f + l1.y - m1.y*m1.y - expf(l1.y))
                 + (1.f + l1.z - m1.z*m1.z - expf(l1.z))
                 + (1.f + l1.w - m1.w*m1.w - expf(l1.w));
        kl = warpSum(kl);
        if (lane == 0){ s_dot[n] = dp; s_kl[n] = -0.5f * kl; }
    }
    __syncthreads();

    if (tid == 0){
        float lg[N_], nm[N_];
        float qkb = g_qkb[b], b2 = bm2_b[0];
        float mx = -3.4e38f;
        for (int n = 0; n < N_; n++){
            int row = b * N_ + n;
            float m = comm[row];
            nm[n] = m;
            float l;
            if (m < 0.5f) l = -1e9f;
            else l = (s_dot[n] + qkb) * 0.0625f - (g_bias[row] + b2)
                     + logf(trust[row] + 1e-6f);
            lg[n] = l;
            mx = fmaxf(mx, l);
        }
        float se = 0.f;
        for (int n = 0; n < N_; n++) se += expf(lg[n] - mx);
        float wsum = 0.f;
        for (int n = 0; n < N_; n++){
            float w = expf(lg[n] - mx) / se * nm[n];
            s_w[n] = w; wsum += w;
        }
        float denom = fmaxf(wsum, 1e-6f);
        float tot = 0.f, klp = 0.f, nmp = 0.f;
        for (int n = 0; n < N_; n++){
            s_w[n] /= denom;
            tot += s_w[n];
            klp += s_kl[n] * nm[n];
            nmp += nm[n];
        }
        g_sw[b] = tot;
        atomicAdd(&g_klsum, klp);
        atomicAdd(&g_nmsum, nmp);
    }
    __syncthreads();

    float acc = 0.f;
    #pragma unroll 8
    for (int n = 0; n < N_; n++) acc += s_w[n] * zsh[n * L_ + tid];
    g_ctx[(size_t)b * L_ + tid] = acc;
}

// ---------------- K5: context@v_w -> @out_w -> comm_feat ----------------
__global__ void k5_out(const float* __restrict__ v_w, const float* __restrict__ v_b,
                       const float* __restrict__ out_w, const float* __restrict__ out_b,
                       float* __restrict__ out){
    __shared__ float s_cx[16][L_];
    __shared__ float s_c2[16][L_];
    __shared__ float s_sw[16];
    int b0 = blockIdx.x * 16;
    int tid = threadIdx.x;
    for (int idx = tid; idx < 16 * L_; idx += 256){
        int r = idx >> 8, l = idx & 255;
        s_cx[r][l] = g_ctx[(size_t)(b0 + r) * L_ + l];
    }
    if (tid < 16) s_sw[tid] = g_sw[b0 + tid];
    __syncthreads();
    {
        float acc[16] = {};
        for (int l = 0; l < L_; l++){
            float w = v_w[(size_t)l * L_ + tid];
            #pragma unroll
            for (int r = 0; r < 16; r++) acc[r] += s_cx[r][l] * w;
        }
        float vb = v_b[tid];
        #pragma unroll
        for (int r = 0; r < 16; r++) s_c2[r][tid] = acc[r] + vb * s_sw[r];
    }
    __syncthreads();
    for (int hh = 0; hh < 2; hh++){
        int h = tid + hh * 256;
        float acc[16] = {};
        for (int l = 0; l < L_; l++){
            float w = out_w[(size_t)l * H_ + h];
            #pragma unroll
            for (int r = 0; r < 16; r++) acc[r] += s_c2[r][l] * w;
        }
        float ob = out_b[h];
        #pragma unroll
        for (int r = 0; r < 16; r++) out[(size_t)(b0 + r) * H_ + h] = acc[r] + ob;
    }
}

// ---------------- K6: kl scalars ----------------
__global__ void k6_kl(float* __restrict__ out){
    float klraw = g_klsum / fmaxf(g_nmsum, 1.f);
    out[(size_t)B_ * H_]     = 0.01f * klraw;
    out[(size_t)B_ * H_ + 1] = klraw;
}

// ---------------- launch ----------------
extern "C" void kernel_launch(void* const* d_in, const int* in_sizes, int n_in,
                              void* d_out, int out_size){
    const float* self   = (const float*)d_in[0];
    const float* neigh  = (const float*)d_in[1];
    const float* trust  = (const float*)d_in[2];
    const float* comm   = (const float*)d_in[3];
    const float* eps    = (const float*)d_in[4];
    const float* pre_w  = (const float*)d_in[5];
    const float* pre_b  = (const float*)d_in[6];
    const float* mu_w   = (const float*)d_in[7];
    const float* mu_b   = (const float*)d_in[8];
    const float* lv_w   = (const float*)d_in[9];
    const float* lv_b   = (const float*)d_in[10];
    const float* post_w = (const float*)d_in[11];
    const float* post_b = (const float*)d_in[12];
    const float* q_w    = (const float*)d_in[13];
    const float* q_b    = (const float*)d_in[14];
    const float* k_w    = (const float*)d_in[15];
    const float* k_b    = (const float*)d_in[16];
    const float* v_w    = (const float*)d_in[17];
    const float* v_b    = (const float*)d_in[18];
    const float* out_w  = (const float*)d_in[19];
    const float* out_b  = (const float*)d_in[20];
    const float* bm1_w  = (const float*)d_in[21];
    const float* bm1_b  = (const float*)d_in[22];
    const float* bm2_w  = (const float*)d_in[23];
    const float* bm2_b  = (const float*)d_in[24];
    float* out = (float*)d_out;

    static bool attr_done = false;
    if (!attr_done){
        cudaFuncSetAttribute(k34_fused, cudaFuncAttributeMaxDynamicSharedMemorySize,
                             N_ * L_ * sizeof(float));
        attr_done = true;
    }

    kw_conv<<<H_ * H_ / 256, 256>>>(mu_w, lv_w, bm1_w);
    k0_stats<<<M_ / 8, 256>>>(neigh);
    k1_query<<<B_ / 8, 256>>>(self, q_w, q_b, k_w, k_b);
    gemm_fused<<<dim3(8, M_ / BMg), 128>>>(neigh, self, pre_w, pre_b,
                                           mu_b, lv_b, bm1_b, bm2_w);
    k34_fused<<<B_, 256, N_ * L_ * sizeof(float)>>>(eps, post_w, post_b, trust, comm, bm2_b);
    k5_out<<<B_ / 16, 256>>>(v_w, v_b, out_w, out_b, out);
    k6_kl<<<1, 1>>>(out);
}

// round 14
// speedup vs baseline: 1.1038x; 1.1038x over previous
#include <cuda_runtime.h>
#include <math.h>
#include <stdint.h>

#define B_  2048
#define N_  64
#define H_  512
#define L_  256
#define M_  (B_*N_)    // 131072 edges

// ---------------- scratch ----------------
__device__ float g_mu [ (size_t)M_ * L_ ];
__device__ float g_lv [ (size_t)M_ * L_ ];
__device__ float g_mean[M_];
__device__ float g_rstd[M_];
__device__ float g_bias[M_];
__device__ float g_qk  [B_ * L_];
__device__ float g_qkb [B_];
__device__ float g_ctx [B_ * L_];
__device__ float g_sw  [B_];
__device__ float g_klsum;
__device__ float g_nmsum;
// pre-converted tf32 weights, TRANSPOSED to [n][k] (k pitch = H_)
__device__ uint32_t g_muw_t [L_ * H_];
__device__ uint32_t g_lvw_t [L_ * H_];
__device__ uint32_t g_bm1w_t[H_ * H_];

// ---------------- helpers ----------------
__device__ __forceinline__ uint32_t f2tf(float x){
    uint32_t u; asm("cvt.rna.tf32.f32 %0, %1;" : "=r"(u) : "f"(x)); return u;
}
__device__ __forceinline__ void mma_tf32(float4& d, const uint32_t a[4], const uint32_t b[2]){
    asm volatile("mma.sync.aligned.m16n8k8.row.col.f32.tf32.tf32.f32 "
        "{%0,%1,%2,%3}, {%4,%5,%6,%7}, {%8,%9}, {%0,%1,%2,%3};\n"
        : "+f"(d.x), "+f"(d.y), "+f"(d.z), "+f"(d.w)
        : "r"(a[0]), "r"(a[1]), "r"(a[2]), "r"(a[3]), "r"(b[0]), "r"(b[1]));
}
__device__ __forceinline__ void ldsm_x4(uint32_t a[4], uint32_t addr){
    asm volatile("ldmatrix.sync.aligned.m8n8.x4.shared.b16 {%0,%1,%2,%3}, [%4];"
        : "=r"(a[0]), "=r"(a[1]), "=r"(a[2]), "=r"(a[3]) : "r"(addr));
}
__device__ __forceinline__ void ldsm_x2(uint32_t b[2], uint32_t addr){
    asm volatile("ldmatrix.sync.aligned.m8n8.x2.shared.b16 {%0,%1}, [%2];"
        : "=r"(b[0]), "=r"(b[1]) : "r"(addr));
}
__device__ __forceinline__ float warpSum(float v){
    #pragma unroll
    for (int o = 16; o; o >>= 1) v += __shfl_xor_sync(0xffffffffu, v, o);
    return v;
}
__device__ __forceinline__ void cp16(uint32_t dst, const void* src){
    asm volatile("cp.async.cg.shared.global [%0], [%1], 16;" :: "r"(dst), "l"(src));
}
#define CP_COMMIT() asm volatile("cp.async.commit_group;")
#define CP_WAIT0()  asm volatile("cp.async.wait_group 0;")

// ---------------- KW: convert weights to tf32, transposed [n][k] ----------------
__global__ void kw_conv(const float* __restrict__ mu_w, const float* __restrict__ lv_w,
                        const float* __restrict__ bm1_w){
    int i = blockIdx.x * 256 + threadIdx.x;   // covers H_*H_
    int n = i >> 9, k = i & 511;
    g_bm1w_t[i] = f2tf(bm1_w[(size_t)k * H_ + n]);
    if (n < L_){
        g_muw_t[i] = f2tf(mu_w[(size_t)k * L_ + n]);
        g_lvw_t[i] = f2tf(lv_w[(size_t)k * L_ + n]);
    }
}

// ---------------- K0: per-row LN stats (warp per row) + zero accumulators --------
__global__ void k0_stats(const float* __restrict__ neigh){
    int row = blockIdx.x * 8 + (threadIdx.x >> 5);
    int lane = threadIdx.x & 31;
    const float4* x = (const float4*)(neigh + (size_t)row * H_);
    float s = 0.f, ss = 0.f;
    #pragma unroll
    for (int i = 0; i < 4; i++){
        float4 v = x[lane + 32 * i];
        s  += v.x + v.y + v.z + v.w;
        ss += v.x*v.x + v.y*v.y + v.z*v.z + v.w*v.w;
    }
    s = warpSum(s); ss = warpSum(ss);
    if (lane == 0){
        float mean = s * (1.f / 512.f);
        float var  = ss * (1.f / 512.f) - mean * mean;
        g_mean[row] = mean;
        g_rstd[row] = rsqrtf(var + 1e-5f);
        g_bias[row] = 0.f;
        if (row == 0){ g_klsum = 0.f; g_nmsum = 0.f; }
    }
}

// ---------------- K1: query = self@q_w + q_b ; qk = query@k_w^T ; qkb = query.k_b --
__global__ void k1_query(const float* __restrict__ self,
                         const float* __restrict__ q_w, const float* __restrict__ q_b,
                         const float* __restrict__ k_w, const float* __restrict__ k_b){
    __shared__ float s_self[8][H_];
    __shared__ float s_q[8][L_];
    int b0 = blockIdx.x * 8;
    int tid = threadIdx.x;
    for (int idx = tid; idx < 8 * H_; idx += 256){
        int r = idx >> 9, h = idx & 511;
        s_self[r][h] = self[(size_t)(b0 + r) * H_ + h];
    }
    __syncthreads();
    {
        float acc[8] = {};
        for (int h = 0; h < H_; h++){
            float w = q_w[(size_t)h * L_ + tid];
            #pragma unroll
            for (int r = 0; r < 8; r++) acc[r] += s_self[r][h] * w;
        }
        float qb = q_b[tid];
        #pragma unroll
        for (int r = 0; r < 8; r++) s_q[r][tid] = acc[r] + qb;
    }
    __syncthreads();
    {
        float acc[8] = {};
        for (int l = 0; l < L_; l++){
            float w = k_w[(size_t)tid * L_ + l];
            #pragma unroll
            for (int r = 0; r < 8; r++) acc[r] += s_q[r][l] * w;
        }
        #pragma unroll
        for (int r = 0; r < 8; r++) g_qk[(size_t)(b0 + r) * L_ + tid] = acc[r];
    }
    int w = tid >> 5, lane = tid & 31;
    float p = 0.f;
    for (int l = lane; l < L_; l += 32) p += s_q[w][l] * k_b[l];
    p = warpSum(p);
    if (lane == 0) g_qkb[b0 + w] = p;
}

// ---------------- K2: fused tf32 GEMM, 256 threads, warp tile 32x64, ldmatrix ----
// grid = (8, M_/128). blockIdx.x = n-slice:
//   yy 0,1: mu cols; yy 2,3: lv cols; yy 4..7: bias-MLP cols
#define BMg 128
#define BNg 128
#define BKg 16
#define APITCH 20
#define BPITCH 20

__global__ __launch_bounds__(256)
void gemm_fused(const float* __restrict__ neigh, const float* __restrict__ self,
                const float* __restrict__ pre_w, const float* __restrict__ pre_b,
                const float* __restrict__ mu_b, const float* __restrict__ lv_b,
                const float* __restrict__ bm1_b, const float* __restrict__ bm2w){
    __shared__ __align__(16) uint32_t As[2][BMg * APITCH];   // [m][k] pitch 20
    __shared__ __align__(16) uint32_t Bs[2][BNg * BPITCH];   // [n][k] pitch 20
    __shared__ float s_mean[BMg], s_rstd[BMg];
    __shared__ float s_prew[H_], s_preb[H_];

    int yy = blockIdx.x;
    int m0 = blockIdx.y * BMg;
    int tid = threadIdx.x;               // 0..255
    int lane = tid & 31, w = tid >> 5;   // 8 warps
    bool isBias = (yy >= 4);

    const uint32_t* Bw; const float* biasv; float* C = nullptr; int n0;
    if (yy < 2){ Bw = g_muw_t; biasv = mu_b; C = g_mu; n0 = yy * 128; }
    else if (yy < 4){ Bw = g_lvw_t; biasv = lv_b; C = g_lv; n0 = (yy - 2) * 128; }
    else { Bw = g_bm1w_t; biasv = bm1_b; n0 = (yy - 4) * 128; }

    if (!isBias){
        if (tid < BMg){
            s_mean[tid] = g_mean[m0 + tid];
            s_rstd[tid] = g_rstd[m0 + tid];
        }
        for (int i = tid; i < H_; i += 256){
            s_prew[i] = pre_w[i]; s_preb[i] = pre_b[i];
        }
        __syncthreads();
    }

    int am = tid >> 2;            // 0..63
    int ak = (tid & 3) * 4;       // 0,4,8,12
    int wm = (w & 3) * 32;        // warp tile 32x64
    int wn = (w >> 2) * 64;

    // ldmatrix per-lane address components
    int rowA = (lane & 7) + ((lane >> 3) & 1) * 8;
    int kqA  = (lane >> 4) * 4;
    int rowB = lane & 7;
    int kqB  = ((lane >> 3) & 1) * 4;

    uint32_t as0 = (uint32_t)__cvta_generic_to_shared(&As[0][0]);
    uint32_t as1 = (uint32_t)__cvta_generic_to_shared(&As[1][0]);
    uint32_t bs0 = (uint32_t)__cvta_generic_to_shared(&Bs[0][0]);
    uint32_t bs1 = (uint32_t)__cvta_generic_to_shared(&Bs[1][0]);

    float4 acc[2][8];
    #pragma unroll
    for (int i = 0; i < 2; i++)
        #pragma unroll
        for (int j = 0; j < 8; j++) acc[i][j] = make_float4(0.f, 0.f, 0.f, 0.f);

    const int KT = H_ / BKg;     // 32
    float4 vA0, vA1, vS0, vS1;

    auto LDG_A = [&](int kt){
        int k0 = kt * BKg;
        vA0 = *(const float4*)(neigh + (size_t)(m0 + am) * H_ + k0 + ak);
        vA1 = *(const float4*)(neigh + (size_t)(m0 + am + 64) * H_ + k0 + ak);
        if (isBias){
            vS0 = *(const float4*)(self + (size_t)((m0 + am) >> 6) * H_ + k0 + ak);
            vS1 = *(const float4*)(self + (size_t)((m0 + am + 64) >> 6) * H_ + k0 + ak);
        }
    };
    auto CPA_B = [&](int kt, int buf){
        int k0 = kt * BKg;
        uint32_t base = buf ? bs1 : bs0;
        int row = tid >> 1, q = (tid & 1) * 8;   // two cp16 per thread
        const uint32_t* src = Bw + (size_t)(n0 + row) * H_ + k0 + q;
        uint32_t dst = base + (row * BPITCH + q) * 4;
        cp16(dst, src);
        cp16(dst + 16, src + 4);
    };
    auto STS_A = [&](int buf, int kt){
        int k0 = kt * BKg;
        float x0, x1, x2, x3;
        if (!isBias){
            float mn = s_mean[am], rs = s_rstd[am];
            x0 = (vA0.x - mn) * rs * s_prew[k0+ak+0] + s_preb[k0+ak+0];
            x1 = (vA0.y - mn) * rs * s_prew[k0+ak+1] + s_preb[k0+ak+1];
            x2 = (vA0.z - mn) * rs * s_prew[k0+ak+2] + s_preb[k0+ak+2];
            x3 = (vA0.w - mn) * rs * s_prew[k0+ak+3] + s_preb[k0+ak+3];
        } else {
            x0 = fabsf(vS0.x - vA0.x); x1 = fabsf(vS0.y - vA0.y);
            x2 = fabsf(vS0.z - vA0.z); x3 = fabsf(vS0.w - vA0.w);
        }
        *(uint4*)&As[buf][am * APITCH + ak] =
            make_uint4(f2tf(x0), f2tf(x1), f2tf(x2), f2tf(x3));
        if (!isBias){
            float mn = s_mean[am + 64], rs = s_rstd[am + 64];
            x0 = (vA1.x - mn) * rs * s_prew[k0+ak+0] + s_preb[k0+ak+0];
            x1 = (vA1.y - mn) * rs * s_prew[k0+ak+1] + s_preb[k0+ak+1];
            x2 = (vA1.z - mn) * rs * s_prew[k0+ak+2] + s_preb[k0+ak+2];
            x3 = (vA1.w - mn) * rs * s_prew[k0+ak+3] + s_preb[k0+ak+3];
        } else {
            x0 = fabsf(vS1.x - vA1.x); x1 = fabsf(vS1.y - vA1.y);
            x2 = fabsf(vS1.z - vA1.z); x3 = fabsf(vS1.w - vA1.w);
        }
        *(uint4*)&As[buf][(am + 64) * APITCH + ak] =
            make_uint4(f2tf(x0), f2tf(x1), f2tf(x2), f2tf(x3));
    };

    CPA_B(0, 0); CP_COMMIT();
    LDG_A(0); STS_A(0, 0);
    CP_WAIT0();
    __syncthreads();

    for (int kt = 0; kt < KT; kt++){
        int cur = kt & 1;
        uint32_t abase = cur ? as1 : as0;
        uint32_t bbase = cur ? bs1 : bs0;
        if (kt + 1 < KT){
            CPA_B(kt + 1, cur ^ 1); CP_COMMIT();
            LDG_A(kt + 1);
        }
        #pragma unroll
        for (int ks = 0; ks < 2; ks++){
            int kb = ks * 8;
            uint32_t af[2][4];
            #pragma unroll
            for (int mi = 0; mi < 2; mi++)
                ldsm_x4(af[mi], abase + ((wm + mi * 16 + rowA) * APITCH + kb + kqA) * 4);
            #pragma unroll
            for (int ni = 0; ni < 8; ni++){
                uint32_t bf[2];
                ldsm_x2(bf, bbase + ((wn + ni * 8 + rowB) * BPITCH + kb + kqB) * 4);
                #pragma unroll
                for (int mi = 0; mi < 2; mi++) mma_tf32(acc[mi][ni], af[mi], bf);
            }
        }
        if (kt + 1 < KT){
            STS_A(cur ^ 1, kt + 1);
            CP_WAIT0();
            __syncthreads();
        }
    }

    if (!isBias){
        #pragma unroll
        for (int mi = 0; mi < 2; mi++){
            int r0 = m0 + wm + mi * 16 + (lane >> 2);
            #pragma unroll
            for (int ni = 0; ni < 8; ni++){
                int c = n0 + wn + ni * 8 + 2 * (lane & 3);
                float b0 = biasv[c], b1 = biasv[c + 1];
                float4 a = acc[mi][ni];
                *(float2*)(C + (size_t)r0 * L_ + c)       = make_float2(a.x + b0, a.y + b1);
                *(float2*)(C + (size_t)(r0 + 8) * L_ + c) = make_float2(a.z + b0, a.w + b1);
            }
        }
    } else {
        __shared__ float brow[BMg];
        if (tid < BMg) brow[tid] = 0.f;
        __syncthreads();
        #pragma unroll
        for (int mi = 0; mi < 2; mi++){
            float s0 = 0.f, s1 = 0.f;
            #pragma unroll
            for (int ni = 0; ni < 8; ni++){
                int c = n0 + wn + ni * 8 + 2 * (lane & 3);
                float w0 = bm2w[c], w1 = bm2w[c + 1];
                float b0 = biasv[c], b1 = biasv[c + 1];
                float4 a = acc[mi][ni];
                s0 += fmaxf(a.x + b0, 0.f) * w0 + fmaxf(a.y + b1, 0.f) * w1;
                s1 += fmaxf(a.z + b0, 0.f) * w0 + fmaxf(a.w + b1, 0.f) * w1;
            }
            s0 += __shfl_xor_sync(0xffffffffu, s0, 1);
            s0 += __shfl_xor_sync(0xffffffffu, s0, 2);
            s1 += __shfl_xor_sync(0xffffffffu, s1, 1);
            s1 += __shfl_xor_sync(0xffffffffu, s1, 2);
            if ((lane & 3) == 0){
                atomicAdd(&brow[wm + mi * 16 + (lane >> 2)], s0);
                atomicAdd(&brow[wm + mi * 16 + (lane >> 2) + 8], s1);
            }
        }
        __syncthreads();
        if (tid < BMg) atomicAdd(&g_bias[m0 + tid], brow[tid]);
    }
}

// ---------------- K34: fused z/LN/kl/dot + softmax + context (block per batch) ----
__global__ void k34_fused(const float* __restrict__ eps,
                          const float* __restrict__ post_w, const float* __restrict__ post_b,
                          const float* __restrict__ trust, const float* __restrict__ comm,
                          const float* __restrict__ bm2_b){
    extern __shared__ float zsh[];   // [64][L_] = 64 KB
    __shared__ float s_dot[N_], s_kl[N_], s_w[N_];
    int b = blockIdx.x, tid = threadIdx.x;
    int wi = tid >> 5, lane = tid & 31;

    float4 pw0 = *(const float4*)(post_w + lane * 4);
    float4 pw1 = *(const float4*)(post_w + 128 + lane * 4);
    float4 pb0 = *(const float4*)(post_b + lane * 4);
    float4 pb1 = *(const float4*)(post_b + 128 + lane * 4);
    float4 qv0 = *(const float4*)(g_qk + (size_t)b * L_ + lane * 4);
    float4 qv1 = *(const float4*)(g_qk + (size_t)b * L_ + 128 + lane * 4);

    #pragma unroll
    for (int j = 0; j < 8; j++){
        int n = wi * 8 + j;
        size_t base = ((size_t)(b * N_ + n)) * L_;
        float4 m0 = *(const float4*)(g_mu + base + lane * 4);
        float4 m1 = *(const float4*)(g_mu + base + 128 + lane * 4);
        float4 l0 = *(const float4*)(g_lv + base + lane * 4);
        float4 l1 = *(const float4*)(g_lv + base + 128 + lane * 4);
        float4 e0 = *(const float4*)(eps + base + lane * 4);
        float4 e1 = *(const float4*)(eps + base + 128 + lane * 4);
        float zp[8];
        zp[0] = m0.x + e0.x * expf(0.5f * l0.x);
        zp[1] = m0.y + e0.y * expf(0.5f * l0.y);
        zp[2] = m0.z + e0.z * expf(0.5f * l0.z);
        zp[3] = m0.w + e0.w * expf(0.5f * l0.w);
        zp[4] = m1.x + e1.x * expf(0.5f * l1.x);
        zp[5] = m1.y + e1.y * expf(0.5f * l1.y);
        zp[6] = m1.z + e1.z * expf(0.5f * l1.z);
        zp[7] = m1.w + e1.w * expf(0.5f * l1.w);
        float s = 0.f;
        #pragma unroll
        for (int i = 0; i < 8; i++) s += zp[i];
        float mean = warpSum(s) * (1.f / 256.f);
        float v = 0.f;
        #pragma unroll
        for (int i = 0; i < 8; i++){ float d = zp[i] - mean; v += d * d; }
        float rstd = rsqrtf(warpSum(v) * (1.f / 256.f) + 1e-5f);
        float4 z0, z1;
        z0.x = (zp[0] - mean) * rstd * pw0.x + pb0.x;
        z0.y = (zp[1] - mean) * rstd * pw0.y + pb0.y;
        z0.z = (zp[2] - mean) * rstd * pw0.z + pb0.z;
        z0.w = (zp[3] - mean) * rstd * pw0.w + pb0.w;
        z1.x = (zp[4] - mean) * rstd * pw1.x + pb1.x;
        z1.y = (zp[5] - mean) * rstd * pw1.y + pb1.y;
        z1.z = (zp[6] - mean) * rstd * pw1.z + pb1.z;
        z1.w = (zp[7] - mean) * rstd * pw1.w + pb1.w;
        *(float4*)(zsh + n * L_ + lane * 4)       = z0;
        *(float4*)(zsh + n * L_ + 128 + lane * 4) = z1;
        float dp = z0.x*qv0.x + z0.y*qv0.y + z0.z*qv0.z + z0.w*qv0.w
                 + z1.x*qv1.x + z1.y*qv1.y + z1.z*qv1.z + z1.w*qv1.w;
        dp = warpSum(dp);
        float kl = (1.f + l0.x - m0.x*m0.x - expf(l0.x))
                 + (1.f + l0.y - m0.y*m0.y - expf(l0.y))
                 + (1.f + l0.z - m0.z*m0.z - expf(l0.z))
                 + (1.f + l0.w - m0.w*m0.w - expf(l0.w))
                 + (1.f + l1.x - m1.x*m1.x - expf(l1.x))
                 + (1.f + l1.y - m1.y*m1.y - expf(l1.y))
                 + (1.f + l1.z - m1.z*m1.z - expf(l1.z))
                 + (1.f + l1.w - m1.w*m1.w - expf(l1.w));
        kl = warpSum(kl);
        if (lane == 0){ s_dot[n] = dp; s_kl[n] = -0.5f * kl; }
    }
    __syncthreads();

    if (tid == 0){
        float lg[N_], nm[N_];
        float qkb = g_qkb[b], b2 = bm2_b[0];
        float mx = -3.4e38f;
        for (int n = 0; n < N_; n++){
            int row = b * N_ + n;
            float m = comm[row];
            nm[n] = m;
            float l;
            if (m < 0.5f) l = -1e9f;
            else l = (s_dot[n] + qkb) * 0.0625f - (g_bias[row] + b2)
                     + logf(trust[row] + 1e-6f);
            lg[n] = l;
            mx = fmaxf(mx, l);
        }
        float se = 0.f;
        for (int n = 0; n < N_; n++) se += expf(lg[n] - mx);
        float wsum = 0.f;
        for (int n = 0; n < N_; n++){
            float w = expf(lg[n] - mx) / se * nm[n];
            s_w[n] = w; wsum += w;
        }
        float denom = fmaxf(wsum, 1e-6f);
        float tot = 0.f, klp = 0.f, nmp = 0.f;
        for (int n = 0; n < N_; n++){
            s_w[n] /= denom;
            tot += s_w[n];
            klp += s_kl[n] * nm[n];
            nmp += nm[n];
        }
        g_sw[b] = tot;
        atomicAdd(&g_klsum, klp);
        atomicAdd(&g_nmsum, nmp);
    }
    __syncthreads();

    float acc = 0.f;
    #pragma unroll 8
    for (int n = 0; n < N_; n++) acc += s_w[n] * zsh[n * L_ + tid];
    g_ctx[(size_t)b * L_ + tid] = acc;
}

// ---------------- K5: context@v_w -> @out_w -> comm_feat ----------------
__global__ void k5_out(const float* __restrict__ v_w, const float* __restrict__ v_b,
                       const float* __restrict__ out_w, const float* __restrict__ out_b,
                       float* __restrict__ out){
    __shared__ float s_cx[16][L_];
    __shared__ float s_c2[16][L_];
    __shared__ float s_sw[16];
    int b0 = blockIdx.x * 16;
    int tid = threadIdx.x;
    for (int idx = tid; idx < 16 * L_; idx += 256){
        int r = idx >> 8, l = idx & 255;
        s_cx[r][l] = g_ctx[(size_t)(b0 + r) * L_ + l];
    }
    if (tid < 16) s_sw[tid] = g_sw[b0 + tid];
    __syncthreads();
    {
        float acc[16] = {};
        for (int l = 0; l < L_; l++){
            float w = v_w[(size_t)l * L_ + tid];
            #pragma unroll
            for (int r = 0; r < 16; r++) acc[r] += s_cx[r][l] * w;
        }
        float vb = v_b[tid];
        #pragma unroll
        for (int r = 0; r < 16; r++) s_c2[r][tid] = acc[r] + vb * s_sw[r];
    }
    __syncthreads();
    for (int hh = 0; hh < 2; hh++){
        int h = tid + hh * 256;
        float acc[16] = {};
        for (int l = 0; l < L_; l++){
            float w = out_w[(size_t)l * H_ + h];
            #pragma unroll
            for (int r = 0; r < 16; r++) acc[r] += s_c2[r][l] * w;
        }
        float ob = out_b[h];
        #pragma unroll
        for (int r = 0; r < 16; r++) out[(size_t)(b0 + r) * H_ + h] = acc[r] + ob;
    }
}

// ---------------- K6: kl scalars ----------------
__global__ void k6_kl(float* __restrict__ out){
    float klraw = g_klsum / fmaxf(g_nmsum, 1.f);
    out[(size_t)B_ * H_]     = 0.01f * klraw;
    out[(size_t)B_ * H_ + 1] = klraw;
}

// ---------------- launch ----------------
extern "C" void kernel_launch(void* const* d_in, const int* in_sizes, int n_in,
                              void* d_out, int out_size){
    const float* self   = (const float*)d_in[0];
    const float* neigh  = (const float*)d_in[1];
    const float* trust  = (const float*)d_in[2];
    const float* comm   = (const float*)d_in[3];
    const float* eps    = (const float*)d_in[4];
    const float* pre_w  = (const float*)d_in[5];
    const float* pre_b  = (const float*)d_in[6];
    const float* mu_w   = (const float*)d_in[7];
    const float* mu_b   = (const float*)d_in[8];
    const float* lv_w   = (const float*)d_in[9];
    const float* lv_b   = (const float*)d_in[10];
    const float* post_w = (const float*)d_in[11];
    const float* post_b = (const float*)d_in[12];
    const float* q_w    = (const float*)d_in[13];
    const float* q_b    = (const float*)d_in[14];
    const float* k_w    = (const float*)d_in[15];
    const float* k_b    = (const float*)d_in[16];
    const float* v_w    = (const float*)d_in[17];
    const float* v_b    = (const float*)d_in[18];
    const float* out_w  = (const float*)d_in[19];
    const float* out_b  = (const float*)d_in[20];
    const float* bm1_w  = (const float*)d_in[21];
    const float* bm1_b  = (const float*)d_in[22];
    const float* bm2_w  = (const float*)d_in[23];
    const float* bm2_b  = (const float*)d_in[24];
    float* out = (float*)d_out;

    static bool attr_done = false;
    if (!attr_done){
        cudaFuncSetAttribute(k34_fused, cudaFuncAttributeMaxDynamicSharedMemorySize,
                             N_ * L_ * sizeof(float));
        attr_done = true;
    }

    kw_conv<<<H_ * H_ / 256, 256>>>(mu_w, lv_w, bm1_w);
    k0_stats<<<M_ / 8, 256>>>(neigh);
    k1_query<<<B_ / 8, 256>>>(self, q_w, q_b, k_w, k_b);
    gemm_fused<<<dim3(8, M_ / BMg), 256>>>(neigh, self, pre_w, pre_b,
                                           mu_b, lv_b, bm1_b, bm2_w);
    k34_fused<<<B_, 256, N_ * L_ * sizeof(float)>>>(eps, post_w, post_b, trust, comm, bm2_b);
    k5_out<<<B_ / 16, 256>>>(v_w, v_b, out_w, out_b, out);
    k6_kl<<<1, 1>>>(out);
}